// round 16
// baseline (speedup 1.0000x reference)
#include <cuda_runtime.h>
#include <math.h>

#define GAMMA_F 0.99f
#define TAU 64          // tau == tauP == 64 (fixed)
#define BPB 4           // batch elements per block (= warps per block)
#define THREADS 128
#define FULL 0xffffffffu

__device__ __forceinline__ unsigned long long make_evict_last_policy() {
    unsigned long long pol;
    asm volatile("createpolicy.fractional.L2::evict_last.b64 %0, 1.0;" : "=l"(pol));
    return pol;
}
__device__ __forceinline__ float ldg_el(const float* p, unsigned long long pol) {
    float v;
    asm volatile("ld.global.nc.L2::cache_hint.f32 %0, [%1], %2;"
                 : "=f"(v) : "l"(p), "l"(pol));
    return v;
}

// count of elements < v in sorted s[0..63]
__device__ __forceinline__ int lbound64(const float* __restrict__ s, float v) {
    int pos = 0;
    #pragma unroll
    for (int st = 64; st >= 1; st >>= 1) {
        const int np = pos + st;
        if (np <= 64 && s[np - 1] < v) pos = np;
    }
    return pos;
}

// O(tau log tau): per b, sort 64 bellman targets (register bitonic), prefix
// sums E1/E2, then each t evaluates its Σ_tp f·h in closed form (regions
// split at x-1, x, x+1). Gather is page-local; no prelude barrier.
__global__ void __launch_bounds__(THREADS)
iqn_td_fused_kernel(const float* __restrict__ q,          // (tau, B, N)
                    const float* __restrict__ next_n_q,   // (tauP, B, N)
                    const int*   __restrict__ action,     // (B,)
                    const int*   __restrict__ next_action,// (B,)
                    const float* __restrict__ reward,     // (T, B)
                    const int*   __restrict__ done,       // (B,)
                    const float* __restrict__ replay_q,   // (tau, B)
                    const float* __restrict__ weight,     // (B,)
                    float* __restrict__ out,              // out[0]=loss, out[1..B]=td
                    int B, int N, int T, float gamma_T)
{
    const int tid  = threadIdx.x;
    const int lane = tid & 31;
    const int w    = tid >> 5;              // warp -> owns b0 + w in compute
    const int b0   = blockIdx.x * BPB;

    __shared__ float s_qsa[BPB][TAU];       // [b][t]
    __shared__ float s_rq [BPB][TAU];
    __shared__ float s_srt[BPB][TAU];       // targets (then sorted)
    __shared__ float s_E1 [BPB][TAU + 1];   // exclusive prefix sums
    __shared__ float s_E2 [BPB][TAU + 1];
    __shared__ float s_wsum[BPB];

    // ---- gather: lane = (ts = lane>>2, bl = lane&3); per-thread scalars ----
    {
        const unsigned long long pol = make_evict_last_policy();
        const int bl = lane & 3;
        const int ts = lane >> 2;            // 0..7
        const int bg = b0 + bl;

        const int a  = action[bg];
        const int an = next_action[bg];
        float r_sum = 0.0f, g = 1.0f;
        #pragma unroll 4
        for (int tt = 0; tt < T; ++tt) {
            r_sum = fmaf(g, reward[tt * B + bg], r_sum);
            g *= GAMMA_F;
        }
        const float coef = (done[bg] != 0) ? 0.0f : gamma_T;

        const size_t plane = (size_t)B * (size_t)N;
        const size_t rowb  = (size_t)bg * (size_t)N;

        #pragma unroll
        for (int k = 0; k < 2; ++k) {        // t = k*32 + w*8 + ts
            const int t = k * 32 + w * 8 + ts;
            const size_t base = (size_t)t * plane + rowb;
            s_qsa[bl][t] = ldg_el(q + base + a, pol);
            s_srt[bl][t] = fmaf(coef, ldg_el(next_n_q + base + an, pol), r_sum);
            s_rq [bl][t] = replay_q[t * B + bg];
        }
    }
    __syncthreads();

    // ================= warp w processes b = b0 + w =================
    float* __restrict__ srt = s_srt[w];
    float* __restrict__ e1  = s_E1[w];
    float* __restrict__ e2  = s_E2[w];

    // ---- bitonic sort of 64 targets in registers via shfl ----
    float r0 = srt[lane];
    float r1 = srt[lane + 32];

    #pragma unroll
    for (int k = 2; k <= 32; k <<= 1) {
        #pragma unroll
        for (int j = 16; j >= 1; j >>= 1) {
            if (j >= k) continue;            // j runs k/2 .. 1
            const float vp0 = __shfl_xor_sync(FULL, r0, j);
            const float vp1 = __shfl_xor_sync(FULL, r1, j);
            const bool lower = ((lane & j) == 0);
            const bool up0 = ((lane & k) == 0);
            const bool up1 = (((lane + 32) & k) == 0);
            r0 = (up0 == lower) ? fminf(r0, vp0) : fmaxf(r0, vp0);
            r1 = (up1 == lower) ? fminf(r1, vp1) : fmaxf(r1, vp1);
        }
    }
    {   // k = 64 merge: j=32 is the intra-lane exchange
        const float lo = fminf(r0, r1), hi = fmaxf(r0, r1);
        r0 = lo; r1 = hi;
        #pragma unroll
        for (int j = 16; j >= 1; j >>= 1) {
            const float vp0 = __shfl_xor_sync(FULL, r0, j);
            const float vp1 = __shfl_xor_sync(FULL, r1, j);
            const bool lower = ((lane & j) == 0);
            r0 = lower ? fminf(r0, vp0) : fmaxf(r0, vp0);
            r1 = lower ? fminf(r1, vp1) : fmaxf(r1, vp1);
        }
    }
    srt[lane]      = r0;                     // sorted ascending
    srt[lane + 32] = r1;

    // ---- prefix sums: E1[i]=Σ_{<i} tgt, E2[i]=Σ_{<i} tgt² ----
    float p0 = r0, p1 = r1, q0 = r0 * r0, q1 = r1 * r1;
    #pragma unroll
    for (int off = 1; off < 32; off <<= 1) {
        const float a0 = __shfl_up_sync(FULL, p0, off);
        const float a1 = __shfl_up_sync(FULL, p1, off);
        const float c0 = __shfl_up_sync(FULL, q0, off);
        const float c1 = __shfl_up_sync(FULL, q1, off);
        if (lane >= off) { p0 += a0; p1 += a1; q0 += c0; q1 += c1; }
    }
    const float tot0  = __shfl_sync(FULL, p0, 31);
    const float tot0q = __shfl_sync(FULL, q0, 31);
    if (lane == 0) { e1[0] = 0.0f; e2[0] = 0.0f; }
    e1[lane + 1]  = p0;          e2[lane + 1]  = q0;
    e1[lane + 33] = tot0 + p1;   e2[lane + 33] = tot0q + q1;
    __syncwarp();

    // ---- closed-form evaluation for t = lane and t = lane+32 ----
    float acc = 0.0f;
    #pragma unroll
    for (int kk = 0; kk < 2; ++kk) {
        const int   t   = lane + kk * 32;
        const float x   = s_qsa[w][t];
        const float rq  = s_rq[w][t];
        const float rqm = 1.0f - rq;
        const int k1 = lbound64(srt, x - 1.0f);  // A: tgt < x-1
        const int k2 = lbound64(srt, x);         // B: [x-1, x)
        const int k3 = lbound64(srt, x + 1.0f);  // C: [x, x+1)

        const float e1a = e1[k1], e1b = e1[k2], e1c = e1[k3], e1d = e1[TAU];
        const float e2a = e2[k1], e2b = e2[k2], e2c = e2[k3];
        const float x2 = x * x;
        const float vA = rqm * ((float)k1 * (x - 0.5f) - e1a);
        const float vB = rqm * 0.5f *
            ((e2b - e2a) - 2.0f * x * (e1b - e1a) + (float)(k2 - k1) * x2);
        const float vC = rq * 0.5f *
            ((e2c - e2b) - 2.0f * x * (e1c - e1b) + (float)(k3 - k2) * x2);
        const float vD = rq * ((e1d - e1c) - (float)(TAU - k3) * (x + 0.5f));
        acc += (vA + vB) + (vC + vD);
    }

    // ---- warp reduce over t; finalize b ----
    #pragma unroll
    for (int off = 16; off > 0; off >>= 1)
        acc += __shfl_down_sync(FULL, acc, off);
    if (lane == 0) {
        const float td = acc * (1.0f / (float)TAU);   // mean over tauP
        out[1 + b0 + w] = td;
        s_wsum[w] = td * weight[b0 + w];
    }
    __syncthreads();

    if (tid < BPB) {
        float v = s_wsum[tid];
        v += __shfl_down_sync(0x0000000fu, v, 2);
        v += __shfl_down_sync(0x0000000fu, v, 1);
        if (tid == 0)
            atomicAdd(out, v * (1.0f / (float)B));    // one atomic per CTA
    }
}

extern "C" void kernel_launch(void* const* d_in, const int* in_sizes, int n_in,
                              void* d_out, int out_size)
{
    const float* q        = (const float*)d_in[0];
    const float* next_n_q = (const float*)d_in[1];
    const int*   action   = (const int*)  d_in[2];
    const int*   naction  = (const int*)  d_in[3];
    const float* reward   = (const float*)d_in[4];
    const int*   done     = (const int*)  d_in[5];
    const float* replay_q = (const float*)d_in[6];
    const float* weight   = (const float*)d_in[7];

    const int B   = in_sizes[2];
    const int tau = in_sizes[6] / B;
    const int N   = in_sizes[0] / (tau * B);
    const int T   = in_sizes[4] / B;

    float gamma_T = 1.0f;
    for (int i = 0; i < T; ++i) gamma_T *= GAMMA_F;

    float* out = (float*)d_out;

    cudaMemsetAsync(out, 0, sizeof(float), 0);   // zero loss accumulator

    iqn_td_fused_kernel<<<B / BPB, THREADS>>>(q, next_n_q, action, naction,
                                              reward, done, replay_q, weight,
                                              out, B, N, T, gamma_T);
}

// round 17
// speedup vs baseline: 1.1295x; 1.1295x over previous
#include <cuda_runtime.h>
#include <math.h>

#define GAMMA_F 0.99f
#define TAU 64          // tau == tauP == 64 (fixed)
#define BPB 8           // batch elements per block (= warps per block)
#define THREADS 256
#define FULL 0xffffffffu

__device__ __forceinline__ unsigned long long make_evict_last_policy() {
    unsigned long long pol;
    asm volatile("createpolicy.fractional.L2::evict_last.b64 %0, 1.0;" : "=l"(pol));
    return pol;
}
__device__ __forceinline__ float ldg_el(const float* p, unsigned long long pol) {
    float v;
    asm volatile("ld.global.nc.L2::cache_hint.f32 %0, [%1], %2;"
                 : "=f"(v) : "l"(p), "l"(pol));
    return v;
}

// count of elements < v in sorted s[0..63]
__device__ __forceinline__ int lbound64(const float* __restrict__ s, float v) {
    int pos = 0;
    #pragma unroll
    for (int st = 64; st >= 1; st >>= 1) {
        const int np = pos + st;
        if (np <= 64 && s[np - 1] < v) pos = np;
    }
    return pos;
}

// R15 skeleton (best: 12.48us) with ONE change: no prelude barrier — each
// gather thread loads its own per-b scalars (broadcast within lane groups),
// so the gather LDGs issue immediately at kernel start.
__global__ void __launch_bounds__(THREADS)
iqn_td_fused_kernel(const float* __restrict__ q,          // (tau, B, N)
                    const float* __restrict__ next_n_q,   // (tauP, B, N)
                    const int*   __restrict__ action,     // (B,)
                    const int*   __restrict__ next_action,// (B,)
                    const float* __restrict__ reward,     // (T, B)
                    const int*   __restrict__ done,       // (B,)
                    const float* __restrict__ replay_q,   // (tau, B)
                    const float* __restrict__ weight,     // (B,)
                    float* __restrict__ out,              // out[0]=loss, out[1..B]=td
                    int B, int N, int T, float gamma_T)
{
    const int tid  = threadIdx.x;
    const int lane = tid & 31;
    const int w    = tid >> 5;              // warp -> owns b0 + w in compute
    const int b0   = blockIdx.x * BPB;

    __shared__ float s_qsa[BPB][TAU];       // [b][t]
    __shared__ float s_rq [BPB][TAU];
    __shared__ float s_srt[BPB][TAU];       // targets (then sorted)
    __shared__ float s_E1 [BPB][TAU + 1];   // exclusive prefix sums
    __shared__ float s_E2 [BPB][TAU + 1];
    __shared__ float s_wsum[BPB];

    // ---- gather: lane = (ts = lane>>3, bl = lane&7); per-thread scalars ----
    {
        const unsigned long long pol = make_evict_last_policy();
        const int bl = lane & 7;
        const int ts = lane >> 3;            // 0..3
        const int bg = b0 + bl;

        const int a  = action[bg];           // 8 distinct addrs/warp, L1-friendly
        const int an = next_action[bg];
        float r_sum = 0.0f, g = 1.0f;
        #pragma unroll 4
        for (int tt = 0; tt < T; ++tt) {
            r_sum = fmaf(g, reward[tt * B + bg], r_sum);
            g *= GAMMA_F;
        }
        const float coef = (done[bg] != 0) ? 0.0f : gamma_T;

        const size_t plane = (size_t)B * (size_t)N;
        const size_t rowb  = (size_t)bg * (size_t)N;

        #pragma unroll
        for (int k = 0; k < 2; ++k) {        // t = k*32 + w*4 + ts
            const int t = k * 32 + w * 4 + ts;
            const size_t base = (size_t)t * plane + rowb;
            s_qsa[bl][t] = ldg_el(q + base + a, pol);
            s_srt[bl][t] = fmaf(coef, ldg_el(next_n_q + base + an, pol), r_sum);
            s_rq [bl][t] = replay_q[t * B + bg];
        }
    }
    __syncthreads();

    // ================= warp w processes b = b0 + w =================
    float* __restrict__ srt = s_srt[w];
    float* __restrict__ e1  = s_E1[w];
    float* __restrict__ e2  = s_E2[w];

    // ---- bitonic sort of 64 targets in registers via shfl ----
    float r0 = srt[lane];
    float r1 = srt[lane + 32];

    #pragma unroll
    for (int k = 2; k <= 32; k <<= 1) {
        #pragma unroll
        for (int j = 16; j >= 1; j >>= 1) {
            if (j >= k) continue;            // j runs k/2 .. 1
            const float vp0 = __shfl_xor_sync(FULL, r0, j);
            const float vp1 = __shfl_xor_sync(FULL, r1, j);
            const bool lower = ((lane & j) == 0);
            const bool up0 = ((lane & k) == 0);
            const bool up1 = (((lane + 32) & k) == 0);
            r0 = (up0 == lower) ? fminf(r0, vp0) : fmaxf(r0, vp0);
            r1 = (up1 == lower) ? fminf(r1, vp1) : fmaxf(r1, vp1);
        }
    }
    {   // k = 64 merge: j=32 is the intra-lane exchange
        const float lo = fminf(r0, r1), hi = fmaxf(r0, r1);
        r0 = lo; r1 = hi;
        #pragma unroll
        for (int j = 16; j >= 1; j >>= 1) {
            const float vp0 = __shfl_xor_sync(FULL, r0, j);
            const float vp1 = __shfl_xor_sync(FULL, r1, j);
            const bool lower = ((lane & j) == 0);
            r0 = lower ? fminf(r0, vp0) : fmaxf(r0, vp0);
            r1 = lower ? fminf(r1, vp1) : fmaxf(r1, vp1);
        }
    }
    srt[lane]      = r0;                     // sorted ascending
    srt[lane + 32] = r1;

    // ---- prefix sums: E1[i]=Σ_{<i} tgt, E2[i]=Σ_{<i} tgt² ----
    float p0 = r0, p1 = r1, q0 = r0 * r0, q1 = r1 * r1;
    #pragma unroll
    for (int off = 1; off < 32; off <<= 1) {
        const float a0 = __shfl_up_sync(FULL, p0, off);
        const float a1 = __shfl_up_sync(FULL, p1, off);
        const float c0 = __shfl_up_sync(FULL, q0, off);
        const float c1 = __shfl_up_sync(FULL, q1, off);
        if (lane >= off) { p0 += a0; p1 += a1; q0 += c0; q1 += c1; }
    }
    const float tot0  = __shfl_sync(FULL, p0, 31);
    const float tot0q = __shfl_sync(FULL, q0, 31);
    if (lane == 0) { e1[0] = 0.0f; e2[0] = 0.0f; }
    e1[lane + 1]  = p0;          e2[lane + 1]  = q0;
    e1[lane + 33] = tot0 + p1;   e2[lane + 33] = tot0q + q1;
    __syncwarp();

    // ---- closed-form evaluation for t = lane and t = lane+32 ----
    float acc = 0.0f;
    #pragma unroll
    for (int kk = 0; kk < 2; ++kk) {
        const int   t   = lane + kk * 32;
        const float x   = s_qsa[w][t];
        const float rq  = s_rq[w][t];
        const float rqm = 1.0f - rq;
        const int k1 = lbound64(srt, x - 1.0f);  // A: tgt < x-1
        const int k2 = lbound64(srt, x);         // B: [x-1, x)
        const int k3 = lbound64(srt, x + 1.0f);  // C: [x, x+1)

        const float e1a = e1[k1], e1b = e1[k2], e1c = e1[k3], e1d = e1[TAU];
        const float e2a = e2[k1], e2b = e2[k2], e2c = e2[k3];
        const float x2 = x * x;
        const float vA = rqm * ((float)k1 * (x - 0.5f) - e1a);
        const float vB = rqm * 0.5f *
            ((e2b - e2a) - 2.0f * x * (e1b - e1a) + (float)(k2 - k1) * x2);
        const float vC = rq * 0.5f *
            ((e2c - e2b) - 2.0f * x * (e1c - e1b) + (float)(k3 - k2) * x2);
        const float vD = rq * ((e1d - e1c) - (float)(TAU - k3) * (x + 0.5f));
        acc += (vA + vB) + (vC + vD);
    }

    // ---- warp reduce over t; finalize b ----
    #pragma unroll
    for (int off = 16; off > 0; off >>= 1)
        acc += __shfl_down_sync(FULL, acc, off);
    if (lane == 0) {
        const float td = acc * (1.0f / (float)TAU);   // mean over tauP
        out[1 + b0 + w] = td;
        s_wsum[w] = td * weight[b0 + w];
    }
    __syncthreads();

    if (tid < BPB) {
        float v = s_wsum[tid];
        v += __shfl_down_sync(0x000000ffu, v, 4);
        v += __shfl_down_sync(0x000000ffu, v, 2);
        v += __shfl_down_sync(0x000000ffu, v, 1);
        if (tid == 0)
            atomicAdd(out, v * (1.0f / (float)B));    // one atomic per CTA
    }
}

extern "C" void kernel_launch(void* const* d_in, const int* in_sizes, int n_in,
                              void* d_out, int out_size)
{
    const float* q        = (const float*)d_in[0];
    const float* next_n_q = (const float*)d_in[1];
    const int*   action   = (const int*)  d_in[2];
    const int*   naction  = (const int*)  d_in[3];
    const float* reward   = (const float*)d_in[4];
    const int*   done     = (const int*)  d_in[5];
    const float* replay_q = (const float*)d_in[6];
    const float* weight   = (const float*)d_in[7];

    const int B   = in_sizes[2];
    const int tau = in_sizes[6] / B;
    const int N   = in_sizes[0] / (tau * B);
    const int T   = in_sizes[4] / B;

    float gamma_T = 1.0f;
    for (int i = 0; i < T; ++i) gamma_T *= GAMMA_F;

    float* out = (float*)d_out;

    cudaMemsetAsync(out, 0, sizeof(float), 0);   // zero loss accumulator

    iqn_td_fused_kernel<<<B / BPB, THREADS>>>(q, next_n_q, action, naction,
                                              reward, done, replay_q, weight,
                                              out, B, N, T, gamma_T);
}